// round 7
// baseline (speedup 1.0000x reference)
#include <cuda_runtime.h>
#include <cstdint>

#define NXG 100
#define NYG 100
#define NN  (NXG * NYG)                    // 10000 nodes
#define ROWVEC (NN / 4)                    // 2500 float4 per row
#define TOTAL_VEC ((uint32_t)NN * ROWVEC)  // 25,000,000 float4
#define GRID_BLOCKS 1184                   // 8 CTAs/SM * 148 SMs, one wave
#define NWARPS (GRID_BLOCKS * 8)           // 9472 warps

__device__ __forceinline__ void stcs4(float4* p, float4 v) {
    asm volatile("st.global.cs.v4.f32 [%0], {%1, %2, %3, %4};"
                 :: "l"(p), "f"(v.x), "f"(v.y), "f"(v.z), "f"(v.w) : "memory");
}

__device__ __forceinline__ float pow125(float x) {
    return x * sqrtf(sqrtf(x));            // x^1.25, x > 0
}

// Compute row i's <=5 nonzeros and write its window [i-100, i+100] with
// full-width float4 stores. All 32 lanes participate; slot = lane & 3.
__device__ __forceinline__ void do_row(
    int i, int lane,
    const float* __restrict__ pot,  const float* __restrict__ chan,
    const float* __restrict__ sheet,const float* __restrict__ face_len,
    const float* __restrict__ link_len,
    const int* __restrict__ adj,    const int* __restrict__ lnk,
    const int* __restrict__ face_at_link,
    const int* __restrict__ head,   const int* __restrict__ tail,
    const int* __restrict__ inout,  float* __restrict__ out)
{
    const int s = lane & 3;
    const int j_raw = adj[i * 4 + s];
    const int l_raw = lnk[i * 4 + s];
    const bool bnd   = (inout[i] == 1);
    const bool valid = (j_raw >= 0) && !bnd;

    const int jc = j_raw >= 0 ? j_raw : 0;
    const int lc = l_raw >= 0 ? l_raw : 0;

    const float ll  = link_len[lc];
    const int   h   = head[lc];
    const int   t   = tail[lc];
    const float cl  = chan[lc];
    const int   fal = face_at_link[lc];
    const float cj  = chan[jc];
    const float sj  = sheet[jc];
    const float ci  = chan[i];
    const float si  = sheet[i];

    const float ph  = pot[h];
    const float pt  = pot[t];
    const float sh  = sheet[h];
    const float stt = sheet[t];
    const float fl  = face_len[fal];

    const float K_SHEET = 0.01f;
    const float K_CHAN  = 0.1f;
    const float CAVSP   = 2.0f;
    const float DISS = (float)((1.0 / 917.0 - 1.0 / 1000.0) / 3.34e5);

    const float g  = (ph - pt) / ll;
    const float rg = rsqrtf(fabsf(g));                 // |g|^(-0.5)

    const float chan_q  = -K_CHAN * pow125(cl) * g;
    const float st_link = 0.5f * (sh + stt);
    const float sheet_q = -K_SHEET * pow125(st_link) * rg * g;

    const float cs = 0.5f * (ci + cj);                 // node-indexed (ref quirk)
    const float stv = 0.5f * (si + sj);

    const float sheet_flux = -K_SHEET * pow125(stv) * rg * fl / ll;
    const float chan_flux  = -K_CHAN  * pow125(cs) * fl / ll;
    const float ch_diss    = fabsf(DISS * chan_q * fl);
    const float sh_diss    = fabsf(DISS * sheet_q * CAVSP * fl);

    float term = valid ? (sheet_flux + chan_flux + ch_diss + sh_diss) : 0.0f;

    float diag = term;
    diag += __shfl_xor_sync(0xFFFFFFFFu, diag, 1, 32);
    diag += __shfl_xor_sync(0xFFFFFFFFu, diag, 2, 32);
    if (bnd) diag = 1.0f;

    const int jcol = valid ? j_raw : -1;
    const int   c0 = __shfl_sync(0xFFFFFFFFu, jcol, 0);
    const int   c1 = __shfl_sync(0xFFFFFFFFu, jcol, 1);
    const int   c2 = __shfl_sync(0xFFFFFFFFu, jcol, 2);
    const int   c3 = __shfl_sync(0xFFFFFFFFu, jcol, 3);
    const float v0 = -__shfl_sync(0xFFFFFFFFu, term, 0);
    const float v1 = -__shfl_sync(0xFFFFFFFFu, term, 1);
    const float v2 = -__shfl_sync(0xFFFFFFFFu, term, 2);
    const float v3 = -__shfl_sync(0xFFFFFFFFu, term, 3);

    float4* rowv = reinterpret_cast<float4*>(out + (size_t)i * NN);
    const int wlo = (i >= 100 ? i - 100 : 0) >> 2;
    const int whi = ((i + 100 < NN) ? i + 100 : NN - 1) >> 2;

    for (int w = wlo + lane; w <= whi; w += 32) {
        const int e = w * 4;
        float4 o;
        #pragma unroll
        for (int k = 0; k < 4; ++k) {
            const int c = e + k;
            float r = (c == i)  ? diag : 0.0f;
            r       = (c == c0) ? v0   : r;
            r       = (c == c1) ? v1   : r;
            r       = (c == c2) ? v2   : r;
            r       = (c == c3) ? v3   : r;
            (&o.x)[k] = r;
        }
        stcs4(rowv + w, o);
    }
}

__global__ void __launch_bounds__(256, 8)
sgds_onewave_kernel(const float* __restrict__ pot,
                    const float* __restrict__ chan,
                    const float* __restrict__ sheet,
                    const float* __restrict__ face_len,
                    const float* __restrict__ link_len,
                    const int*   __restrict__ adj,
                    const int*   __restrict__ lnk,
                    const int*   __restrict__ face_at_link,
                    const int*   __restrict__ head,
                    const int*   __restrict__ tail,
                    const int*   __restrict__ inout,
                    float*       __restrict__ out)
{
    const int tid  = threadIdx.x;
    const int lane = tid & 31;
    const int gw   = blockIdx.x * 8 + (tid >> 5);    // global warp id

    // ---- phase 1: grid-stride zero fill, skipping nonzero windows ----
    float4* outv = reinterpret_cast<float4*>(out);
    const float4 z = make_float4(0.f, 0.f, 0.f, 0.f);
    const uint32_t stride = GRID_BLOCKS * 256u;
    for (uint32_t idx = blockIdx.x * 256u + tid; idx < TOTAL_VEC; idx += stride) {
        const uint32_t i = idx / ROWVEC;             // row (const-div -> mulhi)
        const uint32_t c = idx - i * ROWVEC;         // col vector within row
        const uint32_t lo = (i >= 100u ? i - 100u : 0u) >> 2;
        const uint32_t hi = ((i + 100u < NN) ? i + 100u : NN - 1u) >> 2;
        if (c < lo || c > hi) stcs4(outv + idx, z);
    }

    // ---- phase 2: windows (disjoint addresses; no sync needed) ----
    do_row(gw, lane, pot, chan, sheet, face_len, link_len,
           adj, lnk, face_at_link, head, tail, inout, out);
    const int i2 = gw + NWARPS;
    if (i2 < NN) {
        do_row(i2, lane, pot, chan, sheet, face_len, link_len,
               adj, lnk, face_at_link, head, tail, inout, out);
    }
}

extern "C" void kernel_launch(void* const* d_in, const int* in_sizes, int n_in,
                              void* d_out, int out_size)
{
    const float* pot          = (const float*)d_in[0];
    const float* channel_size = (const float*)d_in[1];
    const float* sheet        = (const float*)d_in[2];
    const float* face_len     = (const float*)d_in[3];
    const float* link_len     = (const float*)d_in[4];
    const int*   adj          = (const int*)d_in[5];
    const int*   lnk          = (const int*)d_in[6];
    const int*   face_at_link = (const int*)d_in[7];
    const int*   head         = (const int*)d_in[8];
    const int*   tail         = (const int*)d_in[9];
    const int*   inout        = (const int*)d_in[10];

    float* out = (float*)d_out;

    sgds_onewave_kernel<<<GRID_BLOCKS, 256>>>(pot, channel_size, sheet,
                                              face_len, link_len, adj, lnk,
                                              face_at_link, head, tail,
                                              inout, out);
}

// round 8
// speedup vs baseline: 1.0620x; 1.0620x over previous
#include <cuda_runtime.h>
#include <cstdint>

#define NXG 100
#define NYG 100
#define NN  (NXG * NYG)                   // 10000 nodes
#define ROWS_PER_BLOCK 8                  // 8 warps/block, 1 warp per row

__device__ __forceinline__ void stcs4(float4* p, float4 v) {
    asm volatile("st.global.cs.v4.f32 [%0], {%1, %2, %3, %4};"
                 :: "l"(p), "f"(v.x), "f"(v.y), "f"(v.z), "f"(v.w) : "memory");
}

__device__ __forceinline__ float pow125(float x) {
    return x * sqrtf(sqrtf(x));           // x^1.25, x > 0
}

// One warp per row: compute the <=5 nonzeros and overwrite the row's
// window [i-100, i+100] (<=51 float4) with full-width stores.
__global__ void __launch_bounds__(256)
sgds_window_kernel(const float* __restrict__ pot,
                   const float* __restrict__ chan,
                   const float* __restrict__ sheet,
                   const float* __restrict__ face_len,
                   const float* __restrict__ link_len,
                   const int*   __restrict__ adj,
                   const int*   __restrict__ lnk,
                   const int*   __restrict__ face_at_link,
                   const int*   __restrict__ head,
                   const int*   __restrict__ tail,
                   const int*   __restrict__ inout,
                   float*       __restrict__ out)
{
    const int lane = threadIdx.x & 31;
    const int s    = lane & 3;            // slot (replicated across lane nibbles)
    const int i    = blockIdx.x * ROWS_PER_BLOCK + (threadIdx.x >> 5);
    if (i >= NN) return;

    const int j_raw = adj[i * 4 + s];
    const int l_raw = lnk[i * 4 + s];
    const bool bnd   = (inout[i] == 1);
    const bool valid = (j_raw >= 0) && !bnd;

    const int jc = j_raw >= 0 ? j_raw : 0;
    const int lc = l_raw >= 0 ? l_raw : 0;

    const float ll  = link_len[lc];
    const int   h   = head[lc];
    const int   t   = tail[lc];
    const float cl  = chan[lc];
    const int   fal = face_at_link[lc];
    const float cj  = chan[jc];
    const float sj  = sheet[jc];
    const float ci  = chan[i];
    const float si  = sheet[i];

    const float ph  = pot[h];
    const float pt  = pot[t];
    const float sh  = sheet[h];
    const float stt = sheet[t];
    const float fl  = face_len[fal];

    const float K_SHEET = 0.01f;
    const float K_CHAN  = 0.1f;
    const float CAVSP   = 2.0f;
    const float DISS = (float)((1.0 / 917.0 - 1.0 / 1000.0) / 3.34e5);

    const float g  = (ph - pt) / ll;
    const float rg = rsqrtf(fabsf(g));                 // |g|^(-0.5)

    const float chan_q  = -K_CHAN * pow125(cl) * g;
    const float st_link = 0.5f * (sh + stt);
    const float sheet_q = -K_SHEET * pow125(st_link) * rg * g;

    const float cs  = 0.5f * (ci + cj);                // node-indexed (ref quirk)
    const float stv = 0.5f * (si + sj);

    const float sheet_flux = -K_SHEET * pow125(stv) * rg * fl / ll;
    const float chan_flux  = -K_CHAN  * pow125(cs) * fl / ll;
    const float ch_diss    = fabsf(DISS * chan_q * fl);
    const float sh_diss    = fabsf(DISS * sheet_q * CAVSP * fl);

    float term = valid ? (sheet_flux + chan_flux + ch_diss + sh_diss) : 0.0f;

    // diagonal = sum of the 4 slots
    float diag = term;
    diag += __shfl_xor_sync(0xFFFFFFFFu, diag, 1, 32);
    diag += __shfl_xor_sync(0xFFFFFFFFu, diag, 2, 32);
    if (bnd) diag = 1.0f;

    // broadcast (col, -term) of slots 0..3 to all lanes
    const int jcol = valid ? j_raw : -1;
    const int   c0 = __shfl_sync(0xFFFFFFFFu, jcol, 0);
    const int   c1 = __shfl_sync(0xFFFFFFFFu, jcol, 1);
    const int   c2 = __shfl_sync(0xFFFFFFFFu, jcol, 2);
    const int   c3 = __shfl_sync(0xFFFFFFFFu, jcol, 3);
    const float v0 = -__shfl_sync(0xFFFFFFFFu, term, 0);
    const float v1 = -__shfl_sync(0xFFFFFFFFu, term, 1);
    const float v2 = -__shfl_sync(0xFFFFFFFFu, term, 2);
    const float v3 = -__shfl_sync(0xFFFFFFFFu, term, 3);

    float4* rowv = reinterpret_cast<float4*>(out + (size_t)i * NN);
    const int wlo = (i >= 100 ? i - 100 : 0) >> 2;
    const int whi = ((i + 100 < NN) ? i + 100 : NN - 1) >> 2;

    for (int w = wlo + lane; w <= whi; w += 32) {
        const int e = w * 4;
        float4 o;
        #pragma unroll
        for (int k = 0; k < 4; ++k) {
            const int c = e + k;
            float r = (c == i)  ? diag : 0.0f;
            r       = (c == c0) ? v0   : r;
            r       = (c == c1) ? v1   : r;
            r       = (c == c2) ? v2   : r;
            r       = (c == c3) ? v3   : r;
            (&o.x)[k] = r;
        }
        stcs4(rowv + w, o);
    }
}

extern "C" void kernel_launch(void* const* d_in, const int* in_sizes, int n_in,
                              void* d_out, int out_size)
{
    const float* pot          = (const float*)d_in[0];
    const float* channel_size = (const float*)d_in[1];
    const float* sheet        = (const float*)d_in[2];
    const float* face_len     = (const float*)d_in[3];
    const float* link_len     = (const float*)d_in[4];
    const int*   adj          = (const int*)d_in[5];
    const int*   lnk          = (const int*)d_in[6];
    const int*   face_at_link = (const int*)d_in[7];
    const int*   head         = (const int*)d_in[8];
    const int*   tail         = (const int*)d_in[9];
    const int*   inout        = (const int*)d_in[10];

    float* out = (float*)d_out;

    // Driver fill path for the 400 MB of zeros (graph memset node),
    // then overwrite the nonzero windows (same-stream ordering).
    cudaMemsetAsync(out, 0, (size_t)NN * NN * sizeof(float));
    sgds_window_kernel<<<NN / ROWS_PER_BLOCK, 256>>>(pot, channel_size, sheet,
                                                     face_len, link_len, adj, lnk,
                                                     face_at_link, head, tail,
                                                     inout, out);
}

// round 9
// speedup vs baseline: 1.0662x; 1.0039x over previous
#include <cuda_runtime.h>
#include <cstdint>

#define NXG 100
#define NYG 100
#define NN  (NXG * NYG)                   // 10000 nodes
#define ROWS_PER_WARP 2
#define WARPS_PER_BLOCK 8
#define BLOCKS (NN / (ROWS_PER_WARP * WARPS_PER_BLOCK))   // 625 -> one wave

__device__ __forceinline__ void stcs4(float4* p, float4 v) {
    asm volatile("st.global.cs.v4.f32 [%0], {%1, %2, %3, %4};"
                 :: "l"(p), "f"(v.x), "f"(v.y), "f"(v.z), "f"(v.w) : "memory");
}

__device__ __forceinline__ float pow125(float x) {
    return x * sqrtf(sqrtf(x));           // x^1.25, x > 0
}

__global__ void __launch_bounds__(256)
sgds_window_kernel(const float* __restrict__ pot,
                   const float* __restrict__ chan,
                   const float* __restrict__ sheet,
                   const float* __restrict__ face_len,
                   const float* __restrict__ link_len,
                   const int*   __restrict__ adj,
                   const int*   __restrict__ lnk,
                   const int*   __restrict__ face_at_link,
                   const int*   __restrict__ head,
                   const int*   __restrict__ tail,
                   const int*   __restrict__ inout,
                   float*       __restrict__ out)
{
    const int lane = threadIdx.x & 31;
    const int s    = lane & 3;            // slot (replicated across lane nibbles)
    const int gw   = blockIdx.x * WARPS_PER_BLOCK + (threadIdx.x >> 5);

    int   iR[ROWS_PER_WARP];
    int   jrawR[ROWS_PER_WARP], lrawR[ROWS_PER_WARP], ioR[ROWS_PER_WARP];

    // ---- level-1 loads for both rows (independent -> front-batched) ----
    #pragma unroll
    for (int r = 0; r < ROWS_PER_WARP; ++r) {
        const int i = gw * ROWS_PER_WARP + r;
        iR[r]    = i;
        jrawR[r] = adj[i * 4 + s];
        lrawR[r] = lnk[i * 4 + s];
        ioR[r]   = inout[i];
    }

    // ---- level-2 loads ----
    float llR[ROWS_PER_WARP], clR[ROWS_PER_WARP], cjR[ROWS_PER_WARP],
          sjR[ROWS_PER_WARP], ciR[ROWS_PER_WARP], siR[ROWS_PER_WARP];
    int   hR[ROWS_PER_WARP], tR[ROWS_PER_WARP], falR[ROWS_PER_WARP];
    #pragma unroll
    for (int r = 0; r < ROWS_PER_WARP; ++r) {
        const int jc = jrawR[r] >= 0 ? jrawR[r] : 0;
        const int lc = lrawR[r] >= 0 ? lrawR[r] : 0;
        llR[r]  = link_len[lc];
        hR[r]   = head[lc];
        tR[r]   = tail[lc];
        clR[r]  = chan[lc];
        falR[r] = face_at_link[lc];
        cjR[r]  = chan[jc];
        sjR[r]  = sheet[jc];
        ciR[r]  = chan[iR[r]];
        siR[r]  = sheet[iR[r]];
    }

    // ---- level-3 loads ----
    float phR[ROWS_PER_WARP], ptR[ROWS_PER_WARP], shR[ROWS_PER_WARP],
          sttR[ROWS_PER_WARP], flR[ROWS_PER_WARP];
    #pragma unroll
    for (int r = 0; r < ROWS_PER_WARP; ++r) {
        phR[r]  = pot[hR[r]];
        ptR[r]  = pot[tR[r]];
        shR[r]  = sheet[hR[r]];
        sttR[r] = sheet[tR[r]];
        flR[r]  = face_len[falR[r]];
    }

    const float K_SHEET = 0.01f;
    const float K_CHAN  = 0.1f;
    const float CAVSP   = 2.0f;
    const float DISS = (float)((1.0 / 917.0 - 1.0 / 1000.0) / 3.34e5);

    // ---- compute + window stores per row ----
    #pragma unroll
    for (int r = 0; r < ROWS_PER_WARP; ++r) {
        const int  i     = iR[r];
        const bool bnd   = (ioR[r] == 1);
        const bool valid = (jrawR[r] >= 0) && !bnd;

        const float g  = (phR[r] - ptR[r]) / llR[r];
        const float rg = rsqrtf(fabsf(g));                 // |g|^(-0.5)

        const float chan_q  = -K_CHAN * pow125(clR[r]) * g;
        const float st_link = 0.5f * (shR[r] + sttR[r]);
        const float sheet_q = -K_SHEET * pow125(st_link) * rg * g;

        const float cs  = 0.5f * (ciR[r] + cjR[r]);        // node-indexed (ref quirk)
        const float stv = 0.5f * (siR[r] + sjR[r]);
        const float fl  = flR[r];
        const float ll  = llR[r];

        const float sheet_flux = -K_SHEET * pow125(stv) * rg * fl / ll;
        const float chan_flux  = -K_CHAN  * pow125(cs) * fl / ll;
        const float ch_diss    = fabsf(DISS * chan_q * fl);
        const float sh_diss    = fabsf(DISS * sheet_q * CAVSP * fl);

        float term = valid ? (sheet_flux + chan_flux + ch_diss + sh_diss) : 0.0f;

        float diag = term;
        diag += __shfl_xor_sync(0xFFFFFFFFu, diag, 1, 32);
        diag += __shfl_xor_sync(0xFFFFFFFFu, diag, 2, 32);
        if (bnd) diag = 1.0f;

        const int jcol = valid ? jrawR[r] : -1;
        const int   c0 = __shfl_sync(0xFFFFFFFFu, jcol, 0);
        const int   c1 = __shfl_sync(0xFFFFFFFFu, jcol, 1);
        const int   c2 = __shfl_sync(0xFFFFFFFFu, jcol, 2);
        const int   c3 = __shfl_sync(0xFFFFFFFFu, jcol, 3);
        const float v0 = -__shfl_sync(0xFFFFFFFFu, term, 0);
        const float v1 = -__shfl_sync(0xFFFFFFFFu, term, 1);
        const float v2 = -__shfl_sync(0xFFFFFFFFu, term, 2);
        const float v3 = -__shfl_sync(0xFFFFFFFFu, term, 3);

        float4* rowv = reinterpret_cast<float4*>(out + (size_t)i * NN);
        const int wlo = (i >= 100 ? i - 100 : 0) >> 2;
        const int whi = ((i + 100 < NN) ? i + 100 : NN - 1) >> 2;

        for (int w = wlo + lane; w <= whi; w += 32) {
            const int e = w * 4;
            float4 o;
            #pragma unroll
            for (int k = 0; k < 4; ++k) {
                const int c = e + k;
                float v = (c == i)  ? diag : 0.0f;
                v       = (c == c0) ? v0   : v;
                v       = (c == c1) ? v1   : v;
                v       = (c == c2) ? v2   : v;
                v       = (c == c3) ? v3   : v;
                (&o.x)[k] = v;
            }
            stcs4(rowv + w, o);
        }
    }
}

extern "C" void kernel_launch(void* const* d_in, const int* in_sizes, int n_in,
                              void* d_out, int out_size)
{
    const float* pot          = (const float*)d_in[0];
    const float* channel_size = (const float*)d_in[1];
    const float* sheet        = (const float*)d_in[2];
    const float* face_len     = (const float*)d_in[3];
    const float* link_len     = (const float*)d_in[4];
    const int*   adj          = (const int*)d_in[5];
    const int*   lnk          = (const int*)d_in[6];
    const int*   face_at_link = (const int*)d_in[7];
    const int*   head         = (const int*)d_in[8];
    const int*   tail         = (const int*)d_in[9];
    const int*   inout        = (const int*)d_in[10];

    float* out = (float*)d_out;

    // Driver fill path for the zeros (graph memset node), then the band.
    cudaMemsetAsync(out, 0, (size_t)NN * NN * sizeof(float));
    sgds_window_kernel<<<BLOCKS, 256>>>(pot, channel_size, sheet,
                                        face_len, link_len, adj, lnk,
                                        face_at_link, head, tail,
                                        inout, out);
}